// round 2
// baseline (speedup 1.0000x reference)
#include <cuda_runtime.h>

// FraudDetectionHybrid: 8 residual tanh layers on [B,2] + Linear(2,1).
//
// Math transform (shift folding): with c_l = sum_{j<=l} shift_j and x_l = y_l + c_l:
//   y_l = y_{l-1} + s_l * tanh(W_l y_{l-1} + (W_l c_{l-1} + b_l))
//   out = W_out y_8 + (W_out c_8 + b_out)
// so shift adds vanish from the inner loop; biases are adjusted once per thread.
//
// tanh via tanh.approx.f32 (1 MUFU op). Predicted MUFU-pipe bound ~55-75us.

__device__ __forceinline__ float tanh_fast(float x) {
    float y;
    asm("tanh.approx.f32 %0, %1;" : "=f"(y) : "f"(x));
    return y;
}

struct __align__(16) Folded {
    float w00, w01, w10, w11;   // layer weights
    float b0, b1;               // adjusted biases (shift folded in)
    float s0, s1;               // scales
};

__global__ void __launch_bounds__(128)
fraud_kernel(const float4* __restrict__ xin,   // 2 rows per float4
             const float*  __restrict__ W,     // [8,2,2]
             const float*  __restrict__ b,     // [8,2]
             const float*  __restrict__ scale, // [8,2]
             const float*  __restrict__ shift, // [8,2]
             const float*  __restrict__ Wout,  // [1,2]
             const float*  __restrict__ bout,  // [1]
             float2*       __restrict__ out,   // 2 outputs per float2
             int npairs)
{
    // ---- fold parameters into registers (once per thread, ~40 flops) ----
    Folded P[8];
    float c0 = 0.f, c1 = 0.f;
#pragma unroll
    for (int l = 0; l < 8; ++l) {
        float w00 = __ldg(&W[l * 4 + 0]);
        float w01 = __ldg(&W[l * 4 + 1]);
        float w10 = __ldg(&W[l * 4 + 2]);
        float w11 = __ldg(&W[l * 4 + 3]);
        P[l].w00 = w00; P[l].w01 = w01; P[l].w10 = w10; P[l].w11 = w11;
        P[l].b0 = fmaf(w00, c0, fmaf(w01, c1, __ldg(&b[l * 2 + 0])));
        P[l].b1 = fmaf(w10, c0, fmaf(w11, c1, __ldg(&b[l * 2 + 1])));
        P[l].s0 = __ldg(&scale[l * 2 + 0]);
        P[l].s1 = __ldg(&scale[l * 2 + 1]);
        c0 += __ldg(&shift[l * 2 + 0]);
        c1 += __ldg(&shift[l * 2 + 1]);
    }
    const float wo0 = __ldg(&Wout[0]);
    const float wo1 = __ldg(&Wout[1]);
    const float bo  = fmaf(wo0, c0, fmaf(wo1, c1, __ldg(&bout[0])));

    const int tid    = blockIdx.x * blockDim.x + threadIdx.x;
    const int stride = gridDim.x * blockDim.x;

    for (int i = tid; i < npairs; i += stride) {
        float4 v = xin[i];                  // rows 2i and 2i+1
        float a0 = v.x, a1 = v.y;           // row A
        float b0v = v.z, b1v = v.w;         // row B
#pragma unroll
        for (int l = 0; l < 8; ++l) {
            // two independent rows -> 2-way ILP through the MUFU chain
            float ua0 = fmaf(P[l].w00, a0,  fmaf(P[l].w01, a1,  P[l].b0));
            float ua1 = fmaf(P[l].w10, a0,  fmaf(P[l].w11, a1,  P[l].b1));
            float ub0 = fmaf(P[l].w00, b0v, fmaf(P[l].w01, b1v, P[l].b0));
            float ub1 = fmaf(P[l].w10, b0v, fmaf(P[l].w11, b1v, P[l].b1));
            float ta0 = tanh_fast(ua0);
            float ta1 = tanh_fast(ua1);
            float tb0 = tanh_fast(ub0);
            float tb1 = tanh_fast(ub1);
            a0  = fmaf(P[l].s0, ta0, a0);
            a1  = fmaf(P[l].s1, ta1, a1);
            b0v = fmaf(P[l].s0, tb0, b0v);
            b1v = fmaf(P[l].s1, tb1, b1v);
        }
        float2 o;
        o.x = fmaf(wo0, a0,  fmaf(wo1, a1,  bo));
        o.y = fmaf(wo0, b0v, fmaf(wo1, b1v, bo));
        out[i] = o;
    }
}

// Tail handler for odd B (defensive; B = 16,777,216 is even).
__global__ void fraud_tail(const float2* __restrict__ xin,
                           const float*  __restrict__ W,
                           const float*  __restrict__ b,
                           const float*  __restrict__ scale,
                           const float*  __restrict__ shift,
                           const float*  __restrict__ Wout,
                           const float*  __restrict__ bout,
                           float*        __restrict__ out,
                           int row)
{
    float x0 = xin[row].x, x1 = xin[row].y;
#pragma unroll
    for (int l = 0; l < 8; ++l) {
        float w00 = W[l*4+0], w01 = W[l*4+1], w10 = W[l*4+2], w11 = W[l*4+3];
        float u0 = fmaf(w00, x0, fmaf(w01, x1, b[l*2+0]));
        float u1 = fmaf(w10, x0, fmaf(w11, x1, b[l*2+1]));
        x0 += fmaf(scale[l*2+0], tanh_fast(u0), shift[l*2+0]);
        x1 += fmaf(scale[l*2+1], tanh_fast(u1), shift[l*2+1]);
    }
    out[row] = fmaf(Wout[0], x0, fmaf(Wout[1], x1, bout[0]));
}

extern "C" void kernel_launch(void* const* d_in, const int* in_sizes, int n_in,
                              void* d_out, int out_size)
{
    const float* x     = (const float*)d_in[0];  // [B,2]
    const float* W     = (const float*)d_in[1];  // [8,2,2]
    const float* b     = (const float*)d_in[2];  // [8,2]
    const float* scale = (const float*)d_in[3];  // [8,2]
    const float* shift = (const float*)d_in[4];  // [8,2]
    const float* Wout  = (const float*)d_in[5];  // [1,2]
    const float* bout  = (const float*)d_in[6];  // [1]
    float* out = (float*)d_out;

    const int B = in_sizes[0] / 2;               // rows
    const int npairs = B / 2;

    const int threads = 128;
    const int blocks  = 148 * 16;                // grid-stride, ~27 iters/thread

    fraud_kernel<<<blocks, threads>>>(
        (const float4*)x, W, b, scale, shift, Wout, bout,
        (float2*)out, npairs);

    if (B & 1) {
        fraud_tail<<<1, 1>>>((const float2*)x, W, b, scale, shift, Wout, bout,
                             out, B - 1);
    }
}

// round 13
// speedup vs baseline: 1.2574x; 1.2574x over previous
#include <cuda_runtime.h>
#include <cstdint>

// FraudDetectionHybrid: 8 residual tanh layers on [B,2] + Linear(2,1).
//
// R2 evidence: latency-bound (occ 32%, issue 38.5%, no pipe saturated; 80 regs,
// 64 of them folded layer params; 2 chains/thread). This version:
//   * folded params live in SMEM, reloaded per layer via volatile LDS.128
//     (ptxas cannot hoist them back into registers)
//   * 4 rows per thread -> 4 independent tanh/fma chains
//   * __launch_bounds__(256, 8) pins regs <= 64 so occupancy >= 16 warps/SM
// Shift folding unchanged (validated: rel_err 2e-6).
// Prediction: 90.2us -> 55-65us.

__device__ __forceinline__ float tanh_fast(float x) {
    float y;
    asm("tanh.approx.f32 %0, %1;" : "=f"(y) : "f"(x));
    return y;
}

__device__ __forceinline__ void lds128(float& a, float& b, float& c, float& d,
                                       uint32_t addr) {
    asm volatile("ld.shared.v4.f32 {%0,%1,%2,%3}, [%4];"
                 : "=f"(a), "=f"(b), "=f"(c), "=f"(d) : "r"(addr));
}

__global__ void __launch_bounds__(256, 8)
fraud_kernel(const float4* __restrict__ xin,   // 2 rows per float4
             const float*  __restrict__ W,     // [8,2,2]
             const float*  __restrict__ b,     // [8,2]
             const float*  __restrict__ scale, // [8,2]
             const float*  __restrict__ shift, // [8,2]
             const float*  __restrict__ Wout,  // [1,2]
             const float*  __restrict__ bout,  // [1]
             float4*       __restrict__ out,   // 4 outputs per float4
             int ngroups)                      // groups of 4 rows
{
    // Layout per layer: [w00 w01 w10 w11][b0' b1' s0 s1]  (8 floats, 32B)
    __shared__ float sp[64];

    if (threadIdx.x == 0) {
        float c0 = 0.f, c1 = 0.f;
#pragma unroll
        for (int l = 0; l < 8; ++l) {
            float w00 = W[l * 4 + 0], w01 = W[l * 4 + 1];
            float w10 = W[l * 4 + 2], w11 = W[l * 4 + 3];
            sp[l * 8 + 0] = w00;
            sp[l * 8 + 1] = w01;
            sp[l * 8 + 2] = w10;
            sp[l * 8 + 3] = w11;
            sp[l * 8 + 4] = fmaf(w00, c0, fmaf(w01, c1, b[l * 2 + 0]));
            sp[l * 8 + 5] = fmaf(w10, c0, fmaf(w11, c1, b[l * 2 + 1]));
            sp[l * 8 + 6] = scale[l * 2 + 0];
            sp[l * 8 + 7] = scale[l * 2 + 1];
            c0 += shift[l * 2 + 0];
            c1 += shift[l * 2 + 1];
        }
    }
    __syncthreads();

    // output layer params (3 regs, loop-invariant)
    float cc0 = 0.f, cc1 = 0.f;
#pragma unroll
    for (int l = 0; l < 8; ++l) { cc0 += __ldg(&shift[l*2+0]); cc1 += __ldg(&shift[l*2+1]); }
    const float wo0 = __ldg(&Wout[0]);
    const float wo1 = __ldg(&Wout[1]);
    const float bo  = fmaf(wo0, cc0, fmaf(wo1, cc1, __ldg(&bout[0])));

    const uint32_t spb = (uint32_t)__cvta_generic_to_shared(sp);

    const int tid    = blockIdx.x * blockDim.x + threadIdx.x;
    const int stride = gridDim.x * blockDim.x;

    for (int i = tid; i < ngroups; i += stride) {
        float4 v0 = xin[2 * i + 0];          // rows 4i, 4i+1
        float4 v1 = xin[2 * i + 1];          // rows 4i+2, 4i+3
        float a0 = v0.x, a1 = v0.y;
        float b0v = v0.z, b1v = v0.w;
        float e0 = v1.x, e1 = v1.y;
        float f0 = v1.z, f1 = v1.w;

#pragma unroll
        for (int l = 0; l < 8; ++l) {
            float w00, w01, w10, w11, pb0, pb1, s0, s1;
            lds128(w00, w01, w10, w11, spb + l * 32);
            lds128(pb0, pb1, s0, s1,  spb + l * 32 + 16);

            // 4 independent rows -> 4-way ILP through MUFU+FMA chains
            float ua0 = fmaf(w00, a0,  fmaf(w01, a1,  pb0));
            float ua1 = fmaf(w10, a0,  fmaf(w11, a1,  pb1));
            float ub0 = fmaf(w00, b0v, fmaf(w01, b1v, pb0));
            float ub1 = fmaf(w10, b0v, fmaf(w11, b1v, pb1));
            float ue0 = fmaf(w00, e0,  fmaf(w01, e1,  pb0));
            float ue1 = fmaf(w10, e0,  fmaf(w11, e1,  pb1));
            float uf0 = fmaf(w00, f0,  fmaf(w01, f1,  pb0));
            float uf1 = fmaf(w10, f0,  fmaf(w11, f1,  pb1));

            a0  = fmaf(s0, tanh_fast(ua0), a0);
            a1  = fmaf(s1, tanh_fast(ua1), a1);
            b0v = fmaf(s0, tanh_fast(ub0), b0v);
            b1v = fmaf(s1, tanh_fast(ub1), b1v);
            e0  = fmaf(s0, tanh_fast(ue0), e0);
            e1  = fmaf(s1, tanh_fast(ue1), e1);
            f0  = fmaf(s0, tanh_fast(uf0), f0);
            f1  = fmaf(s1, tanh_fast(uf1), f1);
        }

        float4 o;
        o.x = fmaf(wo0, a0,  fmaf(wo1, a1,  bo));
        o.y = fmaf(wo0, b0v, fmaf(wo1, b1v, bo));
        o.z = fmaf(wo0, e0,  fmaf(wo1, e1,  bo));
        o.w = fmaf(wo0, f0,  fmaf(wo1, f1,  bo));
        out[i] = o;
    }
}

// Tail: handles rows [first, B) scalar (defensive; B = 16,777,216 is divisible by 4).
__global__ void fraud_tail(const float2* __restrict__ xin,
                           const float*  __restrict__ W,
                           const float*  __restrict__ b,
                           const float*  __restrict__ scale,
                           const float*  __restrict__ shift,
                           const float*  __restrict__ Wout,
                           const float*  __restrict__ bout,
                           float*        __restrict__ out,
                           int first, int B)
{
    for (int row = first; row < B; ++row) {
        float x0 = xin[row].x, x1 = xin[row].y;
#pragma unroll
        for (int l = 0; l < 8; ++l) {
            float w00 = W[l*4+0], w01 = W[l*4+1], w10 = W[l*4+2], w11 = W[l*4+3];
            float u0 = fmaf(w00, x0, fmaf(w01, x1, b[l*2+0]));
            float u1 = fmaf(w10, x0, fmaf(w11, x1, b[l*2+1]));
            x0 += fmaf(scale[l*2+0], tanh_fast(u0), shift[l*2+0]);
            x1 += fmaf(scale[l*2+1], tanh_fast(u1), shift[l*2+1]);
        }
        out[row] = fmaf(Wout[0], x0, fmaf(Wout[1], x1, bout[0]));
    }
}

extern "C" void kernel_launch(void* const* d_in, const int* in_sizes, int n_in,
                              void* d_out, int out_size)
{
    const float* x     = (const float*)d_in[0];  // [B,2]
    const float* W     = (const float*)d_in[1];  // [8,2,2]
    const float* b     = (const float*)d_in[2];  // [8,2]
    const float* scale = (const float*)d_in[3];  // [8,2]
    const float* shift = (const float*)d_in[4];  // [8,2]
    const float* Wout  = (const float*)d_in[5];  // [1,2]
    const float* bout  = (const float*)d_in[6];  // [1]
    float* out = (float*)d_out;

    const int B = in_sizes[0] / 2;               // rows
    const int ngroups = B / 4;                   // 4 rows per thread-iteration

    const int threads = 256;
    const int blocks  = 148 * 8;                 // grid-stride, ~14 iters/thread

    fraud_kernel<<<blocks, threads>>>(
        (const float4*)x, W, b, scale, shift, Wout, bout,
        (float4*)out, ngroups);

    if (B & 3) {
        fraud_tail<<<1, 1>>>((const float2*)x, W, b, scale, shift, Wout, bout,
                             out, ngroups * 4, B);
    }
}